// round 10
// baseline (speedup 1.0000x reference)
#include <cuda_runtime.h>

#define DATA_DIM 512
#define BASIS_DIM 64
#define N_ROWS 2048
#define N_SPANS 61
#define THREADS 256
#define ROWS_TILE 32          // rows per CTA (lane = row)
#define DIMS_TILE 32          // dims per CTA (4 per warp)
#define N_RT (N_ROWS / ROWS_TILE)     // 64 row-tiles
#define N_CH (DATA_DIM / DIMS_TILE)   // 16 dim-chunks
#define X_PITCH 33            // smem pitch: conflict-free column reads

// cross-CTA reduction scratch (zero-init; counter self-resets each replay)
__device__ float g_part[N_RT][N_CH][ROWS_TILE];
__device__ int   g_cnt[N_RT];

// Clamped open-uniform knots: t[g] = clamp(g-3, 0, 61) / 61
__device__ __forceinline__ float knotf(int g) {
    int j = g - 3;
    j = max(0, min(N_SPANS, j));
    return (float)j / (float)N_SPANS;
}

// de Boor weights (polynomial extension) on span m, exact IEEE divides.
// 28 threads, once per CTA. Validated R4/R5/R8/R9 (rel_err ~5e-7).
__device__ float4 deboor_weights(float xx, int m) {
    int k = m + 3;
    float left1  = xx - knotf(k);
    float left2  = xx - knotf(k - 1);
    float left3  = xx - knotf(k - 2);
    float right1 = knotf(k + 1) - xx;
    float right2 = knotf(k + 2) - xx;
    float right3 = knotf(k + 3) - xx;

    float N0 = 1.0f, N1, N2, N3, saved, temp;
    temp = N0 / (right1 + left1);
    N0 = right1 * temp;  N1 = left1 * temp;
    temp = N0 / (right1 + left2);
    N0 = right1 * temp;  saved = left2 * temp;
    temp = N1 / (right2 + left1);
    N1 = saved + right2 * temp;  N2 = left1 * temp;
    temp = N0 / (right1 + left3);
    N0 = right1 * temp;  saved = left3 * temp;
    temp = N1 / (right2 + left2);
    N1 = saved + right2 * temp;  saved = left2 * temp;
    temp = N2 / (right3 + left1);
    N2 = saved + right3 * temp;  N3 = left1 * temp;
    return make_float4(N0, N1, N2, N3);
}

__global__ void __launch_bounds__(THREADS, 6)
bspline_tile2_kernel(const float* __restrict__ x,
                     const float* __restrict__ A,
                     float* __restrict__ out) {
    __shared__ float  x_s[ROWS_TILE * X_PITCH];  // 32 x 32 tile, padded
    __shared__ float4 Wsm[7 * 4];                // boundary-class weight cubics
    __shared__ float  part[8 * 32];              // per-warp row partials

    const int tid  = threadIdx.x;
    const int wid  = tid >> 5;
    const int lane = tid & 31;
    const int ch   = blockIdx.x;   // dim chunk [0,16)
    const int rt   = blockIdx.y;   // row tile  [0,64)

    // ---- stage 32x32 x-tile: one float4 per thread, each row-segment = 1 line ----
    {
        int row = tid >> 3;                 // 8 float4 per 32-dim segment
        int c4  = tid & 7;
        float4 v = __ldg(reinterpret_cast<const float4*>(x)
                         + (size_t)(rt * ROWS_TILE + row) * (DATA_DIM / 4)
                         + ch * (DIMS_TILE / 4) + c4);
        float* d = &x_s[row * X_PITCH + c4 * 4];
        d[0] = v.x; d[1] = v.y; d[2] = v.z; d[3] = v.w;
    }

    // ---- build 7 boundary-class weight cubics (28 threads) ----
    // class c: m<3 -> m ; interior -> 3 ; m>57 -> m-54
    if (tid < 28) {
        int c = tid >> 2, j = tid & 3;
        int m_rep = (c < 3) ? c : ((c == 3) ? 30 : c + 54);
        float f[4];
        #pragma unroll
        for (int s = 0; s < 4; s++) {
            float xs = (float)(3 * m_rep + s) / (3.0f * (float)N_SPANS);
            float4 w = deboor_weights(xs, m_rep);
            f[s] = (j == 0) ? w.x : (j == 1) ? w.y : (j == 2) ? w.z : w.w;
        }
        // exact inverse Vandermonde at nodes {0, 1/3, 2/3, 1}
        float c0 = f[0];
        float c1 = -5.5f * f[0] +  9.0f * f[1] -  4.5f * f[2] +        f[3];
        float c2 =  9.0f * f[0] - 22.5f * f[1] + 18.0f * f[2] - 4.5f * f[3];
        float c3 = -4.5f * f[0] + 13.5f * f[1] - 13.5f * f[2] + 4.5f * f[3];
        Wsm[c * 4 + j] = make_float4(c0, c1, c2, c3);
    }
    __syncthreads();

    // ---- main: warp wid owns 4 dims; lane = row; A rows warp-uniform ----
    float acc = 0.0f;
    const int dbase = wid * 4;

    #pragma unroll
    for (int k = 0; k < 4; k++) {
        int dl = dbase + k;                    // local dim in tile
        int i  = ch * DIMS_TILE + dl;          // global dim
        float xx = x_s[lane * X_PITCH + dl];   // conflict-free column read

        float t = xx * (float)N_SPANS;
        int m = max(0, min(N_SPANS - 1, (int)t));
        float u = t - (float)m;
        int c = (m < 3) ? m : ((m > 57) ? m - 54 : 3);

        float4 p0 = Wsm[c * 4 + 0];
        float4 p1 = Wsm[c * 4 + 1];
        float4 p2 = Wsm[c * 4 + 2];
        float4 p3 = Wsm[c * 4 + 3];
        float w0 = fmaf(fmaf(fmaf(p0.w, u, p0.z), u, p0.y), u, p0.x);
        float w1 = fmaf(fmaf(fmaf(p1.w, u, p1.z), u, p1.y), u, p1.x);
        float w2 = fmaf(fmaf(fmaf(p2.w, u, p2.z), u, p2.y), u, p2.x);
        float w3 = fmaf(fmaf(fmaf(p3.w, u, p3.z), u, p3.y), u, p3.x);

        // warp-uniform A row i: gather touches ~2 lines per LDG
        const float* a = A + i * BASIS_DIM + m;
        acc = fmaf(w0, __ldg(a + 0),
              fmaf(w1, __ldg(a + 1),
              fmaf(w2, __ldg(a + 2),
              fmaf(w3, __ldg(a + 3), acc))));
    }

    // ---- CTA reduce across 8 warps (per row) ----
    part[wid * 32 + lane] = acc;
    __syncthreads();

    if (wid == 0) {
        float s = 0.0f;
        #pragma unroll
        for (int j = 0; j < 8; j++)
            s += part[j * 32 + lane];
        g_part[rt][ch][lane] = s;
        __threadfence();

        int last = 0;
        if (lane == 0) {
            int old = atomicAdd(&g_cnt[rt], 1);
            last = (old == N_CH - 1);
        }
        last = __shfl_sync(0xFFFFFFFFu, last, 0);

        if (last) {
            __threadfence();   // acquire: all chunks' g_part writes visible
            float tot = 0.0f;
            #pragma unroll
            for (int j = 0; j < N_CH; j++)           // fixed order: deterministic
                tot += __ldcg(&g_part[rt][j][lane]); // L2, bypass stale L1
            out[rt * ROWS_TILE + lane] = 1.0f / (1.0f + __expf(-tot));
            if (lane == 0) g_cnt[rt] = 0;   // reset for next graph replay
        }
    }
}

extern "C" void kernel_launch(void* const* d_in, const int* in_sizes, int n_in,
                              void* d_out, int out_size) {
    // Disambiguate by element count: x is 2048*512, A is 512*64.
    const float* x = (const float*)d_in[0];
    const float* A = (const float*)d_in[1];
    if (n_in >= 2 && in_sizes[0] == DATA_DIM * BASIS_DIM &&
        in_sizes[1] == N_ROWS * DATA_DIM) {
        x = (const float*)d_in[1];
        A = (const float*)d_in[0];
    }
    float* out = (float*)d_out;  // [2048]

    dim3 grid(N_CH, N_RT);       // 16 x 64 = 1024 CTAs
    bspline_tile2_kernel<<<grid, THREADS>>>(x, A, out);
}

// round 11
// speedup vs baseline: 1.2851x; 1.2851x over previous
#include <cuda_runtime.h>

#define DATA_DIM 512
#define BASIS_DIM 64
#define N_ROWS 2048
#define N_SPANS 61
#define THREADS 128

// Per-(dim, span) combined cubic: contribution of dim i on span m is
// C0 + C1*u + C2*u^2 + C3*u^3 with u = 61*x - m.   512*61*16 B ≈ 500 KB.
__device__ float4 g_C[DATA_DIM * N_SPANS];

// Clamped open-uniform knots: t[g] = clamp(g-3, 0, 61) / 61
__device__ __forceinline__ float knotf(int g) {
    int j = g - 3;
    j = max(0, min(N_SPANS, j));
    return (float)j / (float)N_SPANS;
}

// de Boor weights (polynomial extension) on span m, exact IEEE divides.
// Runs on 28 threads per init CTA only. Validated R4/R5/R8-R10 (rel_err ~5e-7).
__device__ float4 deboor_weights(float xx, int m) {
    int k = m + 3;
    float left1  = xx - knotf(k);
    float left2  = xx - knotf(k - 1);
    float left3  = xx - knotf(k - 2);
    float right1 = knotf(k + 1) - xx;
    float right2 = knotf(k + 2) - xx;
    float right3 = knotf(k + 3) - xx;

    float N0 = 1.0f, N1, N2, N3, saved, temp;
    temp = N0 / (right1 + left1);
    N0 = right1 * temp;  N1 = left1 * temp;
    temp = N0 / (right1 + left2);
    N0 = right1 * temp;  saved = left2 * temp;
    temp = N1 / (right2 + left1);
    N1 = saved + right2 * temp;  N2 = left1 * temp;
    temp = N0 / (right1 + left3);
    N0 = right1 * temp;  saved = left3 * temp;
    temp = N1 / (right2 + left2);
    N1 = saved + right2 * temp;  saved = left2 * temp;
    temp = N2 / (right3 + left1);
    N2 = saved + right3 * temp;  N3 = left1 * temp;
    return make_float4(N0, N1, N2, N3);
}

// ---- init: C[i][m] = sum_j Wclass(m)_j(u) * A[i][m+j], per-class cubics ----
__global__ void __launch_bounds__(THREADS)
init_coeff_kernel(const float* __restrict__ A) {
    __shared__ float4 Wsm[7 * 4];   // [class][j] cubic coeffs (c0,c1,c2,c3)

    const int tid = threadIdx.x;

    // build 7 boundary-class weight cubics (28 threads per CTA)
    if (tid < 28) {
        int c = tid >> 2, j = tid & 3;
        int m_rep = (c < 3) ? c : ((c == 3) ? 30 : c + 54);
        float f[4];
        #pragma unroll
        for (int s = 0; s < 4; s++) {
            float xs = (float)(3 * m_rep + s) / (3.0f * (float)N_SPANS);
            float4 w = deboor_weights(xs, m_rep);
            f[s] = (j == 0) ? w.x : (j == 1) ? w.y : (j == 2) ? w.z : w.w;
        }
        // exact inverse Vandermonde at nodes {0, 1/3, 2/3, 1}
        float c0 = f[0];
        float c1 = -5.5f * f[0] +  9.0f * f[1] -  4.5f * f[2] +        f[3];
        float c2 =  9.0f * f[0] - 22.5f * f[1] + 18.0f * f[2] - 4.5f * f[3];
        float c3 = -4.5f * f[0] + 13.5f * f[1] - 13.5f * f[2] + 4.5f * f[3];
        Wsm[c * 4 + j] = make_float4(c0, c1, c2, c3);
    }
    __syncthreads();

    int idx = blockIdx.x * THREADS + tid;
    if (idx >= DATA_DIM * N_SPANS) return;
    int i = idx / N_SPANS;          // dim   (lanes share i)
    int m = idx % N_SPANS;          // span  (consecutive across lanes -> coalesced A)
    int c = (m < 3) ? m : ((m > 57) ? m - 54 : 3);

    float a0 = A[i * BASIS_DIM + m + 0];
    float a1 = A[i * BASIS_DIM + m + 1];
    float a2 = A[i * BASIS_DIM + m + 2];
    float a3 = A[i * BASIS_DIM + m + 3];

    float4 w0 = Wsm[c * 4 + 0];
    float4 w1 = Wsm[c * 4 + 1];
    float4 w2 = Wsm[c * 4 + 2];
    float4 w3 = Wsm[c * 4 + 3];

    float4 C;
    C.x = fmaf(w0.x, a0, fmaf(w1.x, a1, fmaf(w2.x, a2, w3.x * a3)));
    C.y = fmaf(w0.y, a0, fmaf(w1.y, a1, fmaf(w2.y, a2, w3.y * a3)));
    C.z = fmaf(w0.z, a0, fmaf(w1.z, a1, fmaf(w2.z, a2, w3.z * a3)));
    C.w = fmaf(w0.w, a0, fmaf(w1.w, a1, fmaf(w2.w, a2, w3.w * a3)));
    g_C[idx] = C;
}

// ---- eval: byte-identical to R4's measured 8.26 us kernel ----
__global__ void __launch_bounds__(THREADS)
bspline_eval_kernel(const float* __restrict__ x, float* __restrict__ out) {
    const int row = blockIdx.x;
    const int tid = threadIdx.x;
    const int i0 = tid * 4;

    const float4 xv = reinterpret_cast<const float4*>(x + (size_t)row * DATA_DIM)[tid];

    float t0 = xv.x * (float)N_SPANS, t1 = xv.y * (float)N_SPANS,
          t2 = xv.z * (float)N_SPANS, t3 = xv.w * (float)N_SPANS;
    int m0 = max(0, min(N_SPANS - 1, (int)t0));
    int m1 = max(0, min(N_SPANS - 1, (int)t1));
    int m2 = max(0, min(N_SPANS - 1, (int)t2));
    int m3 = max(0, min(N_SPANS - 1, (int)t3));
    float u0 = t0 - (float)m0, u1 = t1 - (float)m1,
          u2 = t2 - (float)m2, u3 = t3 - (float)m3;

    float4 c0 = __ldg(&g_C[(i0 + 0) * N_SPANS + m0]);
    float4 c1 = __ldg(&g_C[(i0 + 1) * N_SPANS + m1]);
    float4 c2 = __ldg(&g_C[(i0 + 2) * N_SPANS + m2]);
    float4 c3 = __ldg(&g_C[(i0 + 3) * N_SPANS + m3]);

    float sum = fmaf(fmaf(fmaf(c0.w, u0, c0.z), u0, c0.y), u0, c0.x)
              + fmaf(fmaf(fmaf(c1.w, u1, c1.z), u1, c1.y), u1, c1.x)
              + fmaf(fmaf(fmaf(c2.w, u2, c2.z), u2, c2.y), u2, c2.x)
              + fmaf(fmaf(fmaf(c3.w, u3, c3.z), u3, c3.y), u3, c3.x);

    #pragma unroll
    for (int o = 16; o > 0; o >>= 1)
        sum += __shfl_xor_sync(0xFFFFFFFFu, sum, o);

    __shared__ float ws[THREADS / 32];
    if ((tid & 31) == 0) ws[tid >> 5] = sum;
    __syncthreads();

    if (tid == 0) {
        float s = ws[0] + ws[1] + ws[2] + ws[3];
        out[row] = 1.0f / (1.0f + __expf(-s));
    }
}

extern "C" void kernel_launch(void* const* d_in, const int* in_sizes, int n_in,
                              void* d_out, int out_size) {
    // Disambiguate by element count: x is 2048*512, A is 512*64.
    const float* x = (const float*)d_in[0];
    const float* A = (const float*)d_in[1];
    if (n_in >= 2 && in_sizes[0] == DATA_DIM * BASIS_DIM &&
        in_sizes[1] == N_ROWS * DATA_DIM) {
        x = (const float*)d_in[1];
        A = (const float*)d_in[0];
    }
    float* out = (float*)d_out;  // [2048]

    const int init_items = DATA_DIM * N_SPANS;   // 31232
    init_coeff_kernel<<<(init_items + THREADS - 1) / THREADS, THREADS>>>(A);
    bspline_eval_kernel<<<N_ROWS, THREADS>>>(x, out);
}

// round 12
// speedup vs baseline: 1.3870x; 1.0793x over previous
#include <cuda_runtime.h>

#define DATA_DIM 512
#define BASIS_DIM 64
#define N_ROWS 2048
#define N_SPANS 61
#define THREADS 128

// ---------------- compile-time weight-cubic table ----------------
// For span m, the 4 nonzero cubic basis weights are polynomials in u = 61x - m.
// Only 7 distinct classes exist (m=0,1,2 | interior | m=58,59,60).
// Build them at COMPILE TIME: double-precision de Boor sampled at u={0,1/3,2/3,1}
// + exact inverse Vandermonde. (Construction validated at runtime in R4-R11,
// rel_err ~4.8e-7; double precision here is strictly better.)
namespace ct {

constexpr double knotd(int g) {
    int j = g - 3;
    if (j < 0) j = 0;
    if (j > N_SPANS) j = N_SPANS;
    return (double)j / (double)N_SPANS;
}

struct WTab { float w[7][4][4]; };   // [class][basis j][monomial k]

constexpr WTab make_wtab() {
    WTab T{};
    for (int c = 0; c < 7; c++) {
        int m = (c < 3) ? c : ((c == 3) ? 30 : c + 54);
        double f[4][4] = {};         // [sample][j]
        for (int s = 0; s < 4; s++) {
            double xs = (3.0 * m + s) / (3.0 * (double)N_SPANS);
            double l1 = xs - knotd(m + 3);
            double l2 = xs - knotd(m + 2);
            double l3 = xs - knotd(m + 1);
            double r1 = knotd(m + 4) - xs;
            double r2 = knotd(m + 5) - xs;
            double r3 = knotd(m + 6) - xs;
            double N0 = 1.0, N1 = 0.0, N2 = 0.0, N3 = 0.0, sv = 0.0, tp = 0.0;
            tp = N0 / (r1 + l1); N0 = r1 * tp; N1 = l1 * tp;
            tp = N0 / (r1 + l2); N0 = r1 * tp; sv = l2 * tp;
            tp = N1 / (r2 + l1); N1 = sv + r2 * tp; N2 = l1 * tp;
            tp = N0 / (r1 + l3); N0 = r1 * tp; sv = l3 * tp;
            tp = N1 / (r2 + l2); N1 = sv + r2 * tp; sv = l2 * tp;
            tp = N2 / (r3 + l1); N2 = sv + r3 * tp; N3 = l1 * tp;
            f[s][0] = N0; f[s][1] = N1; f[s][2] = N2; f[s][3] = N3;
        }
        for (int j = 0; j < 4; j++) {
            double f0 = f[0][j], f1 = f[1][j], f2 = f[2][j], f3 = f[3][j];
            T.w[c][j][0] = (float)f0;
            T.w[c][j][1] = (float)(-5.5 * f0 +  9.0 * f1 -  4.5 * f2 +       f3);
            T.w[c][j][2] = (float)( 9.0 * f0 - 22.5 * f1 + 18.0 * f2 - 4.5 * f3);
            T.w[c][j][3] = (float)(-4.5 * f0 + 13.5 * f1 - 13.5 * f2 + 4.5 * f3);
        }
    }
    return T;
}

}  // namespace ct

__constant__ ct::WTab g_W = ct::make_wtab();

// ---------------- fused single kernel ----------------
__device__ __forceinline__ float eval_dim(float xx, const float* __restrict__ A,
                                          int i, const float4* __restrict__ Wsm) {
    float t = xx * (float)N_SPANS;
    int m = max(0, min(N_SPANS - 1, (int)t));
    float u = t - (float)m;
    int c = (m < 3) ? m : ((m > 57) ? m - 54 : 3);

    // issue the 4 A gathers first (in flight during the Horner chain)
    const float* a = A + i * BASIS_DIM + m;
    float a0 = __ldg(a + 0), a1 = __ldg(a + 1), a2 = __ldg(a + 2), a3 = __ldg(a + 3);

    float4 p0 = Wsm[c * 4 + 0];
    float4 p1 = Wsm[c * 4 + 1];
    float4 p2 = Wsm[c * 4 + 2];
    float4 p3 = Wsm[c * 4 + 3];
    float w0 = fmaf(fmaf(fmaf(p0.w, u, p0.z), u, p0.y), u, p0.x);
    float w1 = fmaf(fmaf(fmaf(p1.w, u, p1.z), u, p1.y), u, p1.x);
    float w2 = fmaf(fmaf(fmaf(p2.w, u, p2.z), u, p2.y), u, p2.x);
    float w3 = fmaf(fmaf(fmaf(p3.w, u, p3.z), u, p3.y), u, p3.x);

    return fmaf(w0, a0, fmaf(w1, a1, fmaf(w2, a2, w3 * a3)));
}

__global__ void __launch_bounds__(THREADS)
bspline_fused1_kernel(const float* __restrict__ x,
                      const float* __restrict__ A,
                      float* __restrict__ out) {
    __shared__ float4 Wsm[28];          // [class][j] cubic coeffs
    __shared__ float  ws[THREADS / 32];

    const int row = blockIdx.x;
    const int tid = threadIdx.x;
    const int i0 = tid * 4;

    if (tid < 28) {
        const float* p = g_W.w[tid >> 2][tid & 3];
        Wsm[tid] = make_float4(p[0], p[1], p[2], p[3]);
    }

    // coalesced float4 x load (issued before the barrier; DRAM latency overlaps)
    const float4 xv = reinterpret_cast<const float4*>(x + (size_t)row * DATA_DIM)[tid];
    __syncthreads();

    float sum;
    sum  = eval_dim(xv.x, A, i0 + 0, Wsm);
    sum += eval_dim(xv.y, A, i0 + 1, Wsm);
    sum += eval_dim(xv.z, A, i0 + 2, Wsm);
    sum += eval_dim(xv.w, A, i0 + 3, Wsm);

    #pragma unroll
    for (int o = 16; o > 0; o >>= 1)
        sum += __shfl_xor_sync(0xFFFFFFFFu, sum, o);

    if ((tid & 31) == 0) ws[tid >> 5] = sum;
    __syncthreads();

    if (tid == 0) {
        float s = ws[0] + ws[1] + ws[2] + ws[3];
        out[row] = 1.0f / (1.0f + __expf(-s));
    }
}

extern "C" void kernel_launch(void* const* d_in, const int* in_sizes, int n_in,
                              void* d_out, int out_size) {
    // Disambiguate by element count: x is 2048*512, A is 512*64.
    const float* x = (const float*)d_in[0];
    const float* A = (const float*)d_in[1];
    if (n_in >= 2 && in_sizes[0] == DATA_DIM * BASIS_DIM &&
        in_sizes[1] == N_ROWS * DATA_DIM) {
        x = (const float*)d_in[1];
        A = (const float*)d_in[0];
    }
    float* out = (float*)d_out;  // [2048]
    bspline_fused1_kernel<<<N_ROWS, THREADS>>>(x, A, out);
}